// round 12
// baseline (speedup 1.0000x reference)
#include <cuda_runtime.h>
#include <cuda_bf16.h>
#include <cstdint>

#define E_DIM 128
#define BMAX 1024
#define NTST 32
#define NCID 19
#define NEG_BIG (-3.0e38f)
#define VPW 50432

// ---- static device scratch (allocation-free) ----
__device__ __align__(16) float g_Wt[(size_t)VPW * E_DIM];   // W^T, tf32-rounded
__device__ __align__(16) float g_A [(size_t)BMAX * E_DIM];  // xsembeds, tf32-rounded
__device__ float2 g_stats[(size_t)BMAX * NTST];
__device__ float  g_lse[BMAX];

__device__ __forceinline__ uint32_t smem_u32(const void* p){
  uint32_t a; asm("{ .reg .u64 t; cvta.to.shared.u64 t, %1; cvt.u32.u64 %0, t; }" : "=r"(a) : "l"(p));
  return a;
}
__device__ __forceinline__ float to_tf32(float x){
  uint32_t r; asm("cvt.rna.tf32.f32 %0, %1;" : "=r"(r) : "f"(x));
  return __uint_as_float(r);
}
// swizzled byte offset within a [rows x 128] f32 tile (512B rows, 16B chunks, c in 0..31)
__device__ __forceinline__ uint32_t swoff32(int r, int c){
  return (uint32_t)r*512u + (uint32_t)((c ^ (r & 7)) << 4);
}
__device__ __forceinline__ void cp16(uint32_t dst, const void* src){
  asm volatile("cp.async.cg.shared.global [%0], [%1], 16;" :: "r"(dst), "l"(src) : "memory");
}
#define CP_COMMIT() asm volatile("cp.async.commit_group;" ::: "memory")
#define CP_WAIT(n)  asm volatile("cp.async.wait_group %0;" :: "n"(n) : "memory")

// ldmatrix.x4 on f32-as-b16 (validated R9/R11)
__device__ __forceinline__ void ldm4(uint32_t* f, uint32_t base, int r0, int c0, int lid){
  const uint32_t a = (lid < 16) ? base + swoff32(r0 + lid, c0)
                                : base + swoff32(r0 + lid - 16, c0 + 1);
  asm volatile("ldmatrix.sync.aligned.m8n8.x4.shared.b16 {%0,%1,%2,%3}, [%4];"
    : "=r"(f[0]), "=r"(f[1]), "=r"(f[2]), "=r"(f[3]) : "r"(a));
}
__device__ __forceinline__ void mma_tf32(float* d, const uint32_t* a, const uint32_t* b){
  asm volatile("mma.sync.aligned.m16n8k8.row.col.f32.tf32.tf32.f32 "
    "{%0,%1,%2,%3}, {%4,%5,%6,%7}, {%8,%9}, {%0,%1,%2,%3};"
    : "+f"(d[0]), "+f"(d[1]), "+f"(d[2]), "+f"(d[3])
    : "r"(a[0]), "r"(a[1]), "r"(a[2]), "r"(a[3]), "r"(b[0]), "r"(b[1]));
}
__device__ __forceinline__ void merge(float& m, float& s, float m2, float s2){
  const float nm = fmaxf(m, m2);
  s = s*__expf(m - nm) + s2*__expf(m2 - nm);
  m = nm;
}

// ---------------- K0: fused prep (unchanged) ----------------
__global__ void prep_kernel(const float* __restrict__ W, const float* __restrict__ xs,
                            const float* __restrict__ EM, int V, int NWBLK){
  __shared__ float t[32][33];
  __shared__ int   s_cnt;
  __shared__ int   s_v[1024];
  __shared__ float s_w[1024];
  const int tid = threadIdx.x;

  if ((int)blockIdx.x < NWBLK){
    const int v0 = (blockIdx.x >> 2) * 32, e0 = (blockIdx.x & 3) * 32;
    const int tx = tid & 31, ty = tid >> 5;
#pragma unroll
    for (int k = 0; k < 4; k++){
      const int e = e0 + ty*4 + k, v = v0 + tx;
      t[ty*4+k][tx] = (v < V) ? W[(size_t)e*V + v] : 0.f;
    }
    __syncthreads();
#pragma unroll
    for (int k = 0; k < 4; k++){
      const int a = ty*4 + k;
      g_Wt[(size_t)(v0 + a)*E_DIM + e0 + tx] = to_tf32(t[tx][a]);
    }
    return;
  }

  const int b = blockIdx.x - NWBLK;
  if (tid == 0) s_cnt = 0;
  __syncthreads();

  const float* row = xs + (size_t)b * V;
  int a0 = (int)(((16u - ((unsigned)(uintptr_t)row & 15u)) & 15u) >> 2);
  if (a0 > V) a0 = V;
  const int n4 = (V - a0) >> 2;
  const float4* row4 = (const float4*)(row + a0);

  for (int j = tid; j < n4; j += 256){
    float4 x = row4[j];
    const int base = a0 + 4*j;
    if (x.x != 0.f){ int p = atomicAdd(&s_cnt,1); if (p<1024){ s_v[p]=base;   s_w[p]=x.x; } }
    if (x.y != 0.f){ int p = atomicAdd(&s_cnt,1); if (p<1024){ s_v[p]=base+1; s_w[p]=x.y; } }
    if (x.z != 0.f){ int p = atomicAdd(&s_cnt,1); if (p<1024){ s_v[p]=base+2; s_w[p]=x.z; } }
    if (x.w != 0.f){ int p = atomicAdd(&s_cnt,1); if (p<1024){ s_v[p]=base+3; s_w[p]=x.w; } }
  }
  for (int i = tid; i < a0; i += 256){
    float x = row[i];
    if (x != 0.f){ int p = atomicAdd(&s_cnt,1); if (p<1024){ s_v[p]=i; s_w[p]=x; } }
  }
  for (int i = a0 + 4*n4 + tid; i < V; i += 256){
    float x = row[i];
    if (x != 0.f){ int p = atomicAdd(&s_cnt,1); if (p<1024){ s_v[p]=i; s_w[p]=x; } }
  }
  __syncthreads();

  int cnt = s_cnt; if (cnt > 1024) cnt = 1024;
  if (tid < E_DIM){
    float acc = 0.f;
    for (int k = 0; k < cnt; k++)
      acc = fmaf(s_w[k], EM[(size_t)s_v[k]*E_DIM + tid], acc);
    g_A[(size_t)b*E_DIM + tid] = to_tf32(acc);
  }
}

// ---------------- shared smem layout for both GEMM passes ----------------
#define SM_A   0                       // 64KB
#define SM_W0  65536                   // 64KB
#define SM_W1  131072                  // 64KB
#define SM_STM 196608                  // f32[128][4]
#define SM_STS (196608 + 2048)
#define SMEM_GEMM (196608 + 4096)

// ---------------- K1: pass1 — stats-only persistent GEMM (1 sync/tile) ----------------
__global__ void __launch_bounds__(512, 1)
gemm_stats_kernel(int V, int NTt, int TPC){
  extern __shared__ char smem[];
  const uint32_t sb = smem_u32(smem);
  const int tid = threadIdx.x, wid = tid >> 5, lid = tid & 31;
  const int wm = wid >> 2, wn = wid & 3;
  const int cid = blockIdx.x, mtile = blockIdx.y;
  const int m0 = mtile * 128;
  const int nt0 = cid * TPC;
  const int nt1 = min(NTt, nt0 + TPC);
  if (nt0 >= nt1) return;

  for (int idx = tid; idx < 4096; idx += 512){
    const int r = idx >> 5, c = idx & 31;
    cp16(sb + SM_A + swoff32(r, c), &((const uint4*)g_A)[(size_t)(m0 + r)*32 + c]);
  }
  {
    const int n0 = nt0 * 128;
    for (int idx = tid; idx < 4096; idx += 512){
      const int r = idx >> 5, c = idx & 31;
      cp16(sb + SM_W0 + swoff32(r, c), &((const uint4*)g_Wt)[(size_t)(n0 + r)*32 + c]);
    }
  }
  CP_COMMIT();

  const int rA = 32*wm, rB = 32*wn;
  const int cq = (lid & 3) * 2;
  const int rq = lid >> 2;
  float rm[4], rs[4];
#pragma unroll
  for (int j = 0; j < 4; j++){ rm[j] = NEG_BIG; rs[j] = 0.f; }

  for (int i = nt0; i < nt1; i++){
    const int lb = (i - nt0) & 1;
    const uint32_t wB = sb + (lb ? SM_W1 : SM_W0);
    const int n0 = i * 128;

    CP_WAIT(0);
    __syncthreads();                    // W(i) ready; prior LDSMs done

    if (i + 1 < nt1){
      const uint32_t wN = sb + (lb ? SM_W0 : SM_W1);
      const int nn = (i + 1) * 128;
      for (int idx = tid; idx < 4096; idx += 512){
        const int r = idx >> 5, c = idx & 31;
        cp16(wN + swoff32(r, c), &((const uint4*)g_Wt)[(size_t)(nn + r)*32 + c]);
      }
      CP_COMMIT();
    }

    float d[2][4][4];
#pragma unroll
    for (int mf = 0; mf < 2; mf++)
#pragma unroll
      for (int nf = 0; nf < 4; nf++)
#pragma unroll
        for (int k = 0; k < 4; k++) d[mf][nf][k] = 0.f;

#pragma unroll 4
    for (int s = 0; s < 16; s++){
      const int c0 = 2*s;
      uint32_t a[2][4], b[4][2];
      ldm4(a[0], sb + SM_A, rA,      c0, lid);
      ldm4(a[1], sb + SM_A, rA + 16, c0, lid);
#pragma unroll
      for (int j = 0; j < 2; j++){
        uint32_t t[4];
        ldm4(t, wB, rB + 16*j, c0, lid);
        b[2*j][0]   = t[0]; b[2*j][1]   = t[2];
        b[2*j+1][0] = t[1]; b[2*j+1][1] = t[3];
      }
#pragma unroll
      for (int mf = 0; mf < 2; mf++)
#pragma unroll
        for (int nf = 0; nf < 4; nf++)
          mma_tf32(d[mf][nf], a[mf], b[nf]);
    }

    // ---- stats (registers only; mask padded cols) ----
#pragma unroll
    for (int mf = 0; mf < 2; mf++){
      float mx0 = NEG_BIG, mx1 = NEG_BIG;
#pragma unroll
      for (int nf = 0; nf < 4; nf++){
        const int g = n0 + rB + 8*nf + cq;
        if (g   >= V){ d[mf][nf][0] = NEG_BIG; d[mf][nf][2] = NEG_BIG; }
        if (g+1 >= V){ d[mf][nf][1] = NEG_BIG; d[mf][nf][3] = NEG_BIG; }
        mx0 = fmaxf(mx0, fmaxf(d[mf][nf][0], d[mf][nf][1]));
        mx1 = fmaxf(mx1, fmaxf(d[mf][nf][2], d[mf][nf][3]));
      }
      float s0 = 0.f, s1 = 0.f;
#pragma unroll
      for (int nf = 0; nf < 4; nf++){
        s0 += __expf(d[mf][nf][0]-mx0) + __expf(d[mf][nf][1]-mx0);
        s1 += __expf(d[mf][nf][2]-mx1) + __expf(d[mf][nf][3]-mx1);
      }
      if (mx0 == NEG_BIG) s0 = 0.f;
      if (mx1 == NEG_BIG) s1 = 0.f;
      merge(rm[2*mf],   rs[2*mf],   mx0, s0);
      merge(rm[2*mf+1], rs[2*mf+1], mx1, s1);
    }
  }

  // ---- final reduce: 4 lanes/row, then 4 wn warps via smem ----
  float* smM = (float*)(smem + SM_STM);
  float* smS = (float*)(smem + SM_STS);
#pragma unroll
  for (int j = 0; j < 4; j++){
#pragma unroll
    for (int o = 1; o <= 2; o <<= 1)
      merge(rm[j], rs[j], __shfl_xor_sync(0xFFFFFFFFu, rm[j], o),
                          __shfl_xor_sync(0xFFFFFFFFu, rs[j], o));
  }
  __syncthreads();
  if ((lid & 3) == 0){
#pragma unroll
    for (int j = 0; j < 4; j++){
      const int rloc = rA + 16*(j >> 1) + 8*(j & 1) + rq;
      smM[rloc*4 + wn] = rm[j];
      smS[rloc*4 + wn] = rs[j];
    }
  }
  __syncthreads();
  if (tid < 128){
    float m = NEG_BIG, s = 0.f;
#pragma unroll
    for (int k = 0; k < 4; k++) merge(m, s, smM[tid*4 + k], smS[tid*4 + k]);
    g_stats[(size_t)(m0 + tid)*NTST + cid] = make_float2(m, s);
  }
}

// ---------------- K2: combine stats -> lse ----------------
__global__ void lse_kernel(int B, int NQ){
  const int w = (blockIdx.x * blockDim.x + threadIdx.x) >> 5;
  const int lid = threadIdx.x & 31;
  if (w >= B) return;
  float m = NEG_BIG, s = 0.f;
  for (int q = lid; q < NQ; q += 32){
    const float2 t = g_stats[(size_t)w*NTST + q];
    merge(m, s, t.x, t.y);
  }
#pragma unroll
  for (int o = 16; o; o >>= 1)
    merge(m, s, __shfl_xor_sync(0xFFFFFFFFu, m, o), __shfl_xor_sync(0xFFFFFFFFu, s, o));
  if (lid == 0) g_lse[w] = m + logf(s);
}

// ---------------- K3: pass2 — recompute MMA, subtract lse, coalesced store ----------------
__global__ void __launch_bounds__(512, 1)
gemm_store_kernel(float* __restrict__ out, int V, int NTt, int TPC){
  extern __shared__ char smem[];
  const uint32_t sb = smem_u32(smem);
  const int tid = threadIdx.x, wid = tid >> 5, lid = tid & 31;
  const int wm = wid >> 2, wn = wid & 3;
  const int cid = blockIdx.x, mtile = blockIdx.y;
  const int m0 = mtile * 128;
  const int nt0 = cid * TPC;
  const int nt1 = min(NTt, nt0 + TPC);
  if (nt0 >= nt1) return;

  const int rA = 32*wm, rB = 32*wn;
  const int cq = (lid & 3) * 2;
  const int rq = lid >> 2;

  // per-thread row lse: rows rA+16mf+rq, +8
  float lse4[4];
#pragma unroll
  for (int j = 0; j < 4; j++)
    lse4[j] = g_lse[m0 + rA + 16*(j >> 1) + 8*(j & 1) + rq];

  for (int idx = tid; idx < 4096; idx += 512){
    const int r = idx >> 5, c = idx & 31;
    cp16(sb + SM_A + swoff32(r, c), &((const uint4*)g_A)[(size_t)(m0 + r)*32 + c]);
  }
  {
    const int n0 = nt0 * 128;
    for (int idx = tid; idx < 4096; idx += 512){
      const int r = idx >> 5, c = idx & 31;
      cp16(sb + SM_W0 + swoff32(r, c), &((const uint4*)g_Wt)[(size_t)(n0 + r)*32 + c]);
    }
  }
  CP_COMMIT();

  for (int i = nt0; i < nt1; i++){
    const int lb = (i - nt0) & 1;
    const uint32_t wB = sb + (lb ? SM_W1 : SM_W0);
    const int n0 = i * 128;

    CP_WAIT(0);
    __syncthreads();

    if (i + 1 < nt1){
      const uint32_t wN = sb + (lb ? SM_W0 : SM_W1);
      const int nn = (i + 1) * 128;
      for (int idx = tid; idx < 4096; idx += 512){
        const int r = idx >> 5, c = idx & 31;
        cp16(wN + swoff32(r, c), &((const uint4*)g_Wt)[(size_t)(nn + r)*32 + c]);
      }
      CP_COMMIT();
    }

    float d[2][4][4];
#pragma unroll
    for (int mf = 0; mf < 2; mf++)
#pragma unroll
      for (int nf = 0; nf < 4; nf++)
#pragma unroll
        for (int k = 0; k < 4; k++) d[mf][nf][k] = 0.f;

#pragma unroll 4
    for (int s = 0; s < 16; s++){
      const int c0 = 2*s;
      uint32_t a[2][4], b[4][2];
      ldm4(a[0], sb + SM_A, rA,      c0, lid);
      ldm4(a[1], sb + SM_A, rA + 16, c0, lid);
#pragma unroll
      for (int j = 0; j < 2; j++){
        uint32_t t[4];
        ldm4(t, wB, rB + 16*j, c0, lid);
        b[2*j][0]   = t[0]; b[2*j][1]   = t[2];
        b[2*j+1][0] = t[1]; b[2*j+1][1] = t[3];
      }
#pragma unroll
      for (int mf = 0; mf < 2; mf++)
#pragma unroll
        for (int nf = 0; nf < 4; nf++)
          mma_tf32(d[mf][nf], a[mf], b[nf]);
    }
    __syncthreads();                    // LDSM done: wB reusable as staging

    // ---- stage (logit - lse) into wB, swizzled ----
    char* Lb = smem + (lb ? SM_W1 : SM_W0);
#pragma unroll
    for (int mf = 0; mf < 2; mf++){
      const int rl = rA + 16*mf + rq;
      const float l0 = lse4[2*mf], l1 = lse4[2*mf + 1];
#pragma unroll
      for (int nf = 0; nf < 4; nf++){
        const int cl = rB + 8*nf + cq;
        const uint32_t o0 = swoff32(rl,   cl >> 2) + (cl & 3)*4;
        const uint32_t o1 = swoff32(rl+8, cl >> 2) + (cl & 3)*4;
        *(float2*)(Lb + o0) = make_float2(d[mf][nf][0] - l0, d[mf][nf][1] - l0);
        *(float2*)(Lb + o1) = make_float2(d[mf][nf][2] - l1, d[mf][nf][3] - l1);
      }
    }
    __syncthreads();

    // ---- coalesced store ----
    const int vlim = min(128, V - n0);
#pragma unroll 4
    for (int idx = tid; idx < 128*128; idx += 512){
      const int r = idx >> 7, c = idx & 127;
      if (c < vlim)
        out[(size_t)(m0 + r)*V + n0 + c] =
          *(const float*)(Lb + swoff32(r, c >> 2) + (c & 3)*4);
    }
    __syncthreads();
  }
}

extern "C" void kernel_launch(void* const* d_in, const int* in_sizes, int n_in,
                              void* d_out, int out_size){
  const float* xs = (const float*)d_in[0];
  const float* EM = (const float*)d_in[2];
  const float* W  = (const float*)d_in[3];
  float* out = (float*)d_out;

  const int V   = in_sizes[3] / E_DIM;         // 50257
  const int B   = in_sizes[0] / V;             // 1024
  const int NTt = (V + 127) / 128;             // 393
  const int TPC = (NTt + NCID - 1) / NCID;     // 21
  const int NWBLK = (VPW/32) * 4;              // 6304 wsplit blocks

  cudaFuncSetAttribute(gemm_stats_kernel, cudaFuncAttributeMaxDynamicSharedMemorySize, SMEM_GEMM);
  cudaFuncSetAttribute(gemm_store_kernel, cudaFuncAttributeMaxDynamicSharedMemorySize, SMEM_GEMM);

  prep_kernel<<<NWBLK + B, 256>>>(W, xs, EM, V, NWBLK);
  gemm_stats_kernel<<<dim3(NCID, B/128), 512, SMEM_GEMM>>>(V, NTt, TPC);
  lse_kernel<<<(B*32 + 255)/256, 256>>>(B, NCID);
  gemm_store_kernel<<<dim3(NCID, B/128), 512, SMEM_GEMM>>>(out, V, NTt, TPC);
}

// round 14
// speedup vs baseline: 1.0480x; 1.0480x over previous
#include <cuda_runtime.h>
#include <cuda_bf16.h>
#include <cstdint>

#define E_DIM 128
#define BMAX 1024
#define NTST 32
#define NCID 19
#define NEG_BIG (-3.0e38f)
#define VPW 50432

// ---- static device scratch (allocation-free) ----
__device__ __align__(16) float g_Wt[(size_t)VPW * E_DIM];   // W^T, tf32-rounded
__device__ __align__(16) float g_A [(size_t)BMAX * E_DIM];  // xsembeds, tf32-rounded
__device__ float2 g_stats[(size_t)BMAX * NTST];
__device__ float  g_lse[BMAX];

__device__ __forceinline__ uint32_t smem_u32(const void* p){
  uint32_t a; asm("{ .reg .u64 t; cvta.to.shared.u64 t, %1; cvt.u32.u64 %0, t; }" : "=r"(a) : "l"(p));
  return a;
}
__device__ __forceinline__ float to_tf32(float x){
  uint32_t r; asm("cvt.rna.tf32.f32 %0, %1;" : "=r"(r) : "f"(x));
  return __uint_as_float(r);
}
// swizzled byte offset within a [rows x 128] f32 tile (512B rows, 16B chunks, c in 0..31)
__device__ __forceinline__ uint32_t swoff32(int r, int c){
  return (uint32_t)r*512u + (uint32_t)((c ^ (r & 7)) << 4);
}
__device__ __forceinline__ void cp16(uint32_t dst, const void* src){
  asm volatile("cp.async.cg.shared.global [%0], [%1], 16;" :: "r"(dst), "l"(src) : "memory");
}
#define CP_COMMIT() asm volatile("cp.async.commit_group;" ::: "memory")
#define CP_WAIT(n)  asm volatile("cp.async.wait_group %0;" :: "n"(n) : "memory")

// ldmatrix.x4 on f32-as-b16 (validated R9/R11)
__device__ __forceinline__ void ldm4(uint32_t* f, uint32_t base, int r0, int c0, int lid){
  const uint32_t a = (lid < 16) ? base + swoff32(r0 + lid, c0)
                                : base + swoff32(r0 + lid - 16, c0 + 1);
  asm volatile("ldmatrix.sync.aligned.m8n8.x4.shared.b16 {%0,%1,%2,%3}, [%4];"
    : "=r"(f[0]), "=r"(f[1]), "=r"(f[2]), "=r"(f[3]) : "r"(a));
}
__device__ __forceinline__ void mma_tf32(float* d, const uint32_t* a, const uint32_t* b){
  asm volatile("mma.sync.aligned.m16n8k8.row.col.f32.tf32.tf32.f32 "
    "{%0,%1,%2,%3}, {%4,%5,%6,%7}, {%8,%9}, {%0,%1,%2,%3};"
    : "+f"(d[0]), "+f"(d[1]), "+f"(d[2]), "+f"(d[3])
    : "r"(a[0]), "r"(a[1]), "r"(a[2]), "r"(a[3]), "r"(b[0]), "r"(b[1]));
}
__device__ __forceinline__ void merge(float& m, float& s, float m2, float s2){
  const float nm = fmaxf(m, m2);
  s = s*__expf(m - nm) + s2*__expf(m2 - nm);
  m = nm;
}

// ---------------- K0: fused prep (unchanged) ----------------
__global__ void prep_kernel(const float* __restrict__ W, const float* __restrict__ xs,
                            const float* __restrict__ EM, int V, int NWBLK){
  __shared__ float t[32][33];
  __shared__ int   s_cnt;
  __shared__ int   s_v[1024];
  __shared__ float s_w[1024];
  const int tid = threadIdx.x;

  if ((int)blockIdx.x < NWBLK){
    const int v0 = (blockIdx.x >> 2) * 32, e0 = (blockIdx.x & 3) * 32;
    const int tx = tid & 31, ty = tid >> 5;
#pragma unroll
    for (int k = 0; k < 4; k++){
      const int e = e0 + ty*4 + k, v = v0 + tx;
      t[ty*4+k][tx] = (v < V) ? W[(size_t)e*V + v] : 0.f;
    }
    __syncthreads();
#pragma unroll
    for (int k = 0; k < 4; k++){
      const int a = ty*4 + k;
      g_Wt[(size_t)(v0 + a)*E_DIM + e0 + tx] = to_tf32(t[tx][a]);
    }
    return;
  }

  const int b = blockIdx.x - NWBLK;
  if (tid == 0) s_cnt = 0;
  __syncthreads();

  const float* row = xs + (size_t)b * V;
  int a0 = (int)(((16u - ((unsigned)(uintptr_t)row & 15u)) & 15u) >> 2);
  if (a0 > V) a0 = V;
  const int n4 = (V - a0) >> 2;
  const float4* row4 = (const float4*)(row + a0);

  for (int j = tid; j < n4; j += 256){
    float4 x = row4[j];
    const int base = a0 + 4*j;
    if (x.x != 0.f){ int p = atomicAdd(&s_cnt,1); if (p<1024){ s_v[p]=base;   s_w[p]=x.x; } }
    if (x.y != 0.f){ int p = atomicAdd(&s_cnt,1); if (p<1024){ s_v[p]=base+1; s_w[p]=x.y; } }
    if (x.z != 0.f){ int p = atomicAdd(&s_cnt,1); if (p<1024){ s_v[p]=base+2; s_w[p]=x.z; } }
    if (x.w != 0.f){ int p = atomicAdd(&s_cnt,1); if (p<1024){ s_v[p]=base+3; s_w[p]=x.w; } }
  }
  for (int i = tid; i < a0; i += 256){
    float x = row[i];
    if (x != 0.f){ int p = atomicAdd(&s_cnt,1); if (p<1024){ s_v[p]=i; s_w[p]=x; } }
  }
  for (int i = a0 + 4*n4 + tid; i < V; i += 256){
    float x = row[i];
    if (x != 0.f){ int p = atomicAdd(&s_cnt,1); if (p<1024){ s_v[p]=i; s_w[p]=x; } }
  }
  __syncthreads();

  int cnt = s_cnt; if (cnt > 1024) cnt = 1024;
  if (tid < E_DIM){
    float acc = 0.f;
    for (int k = 0; k < cnt; k++)
      acc = fmaf(s_w[k], EM[(size_t)s_v[k]*E_DIM + tid], acc);
    g_A[(size_t)b*E_DIM + tid] = to_tf32(acc);
  }
}

// ---------------- K1: persistent tf32 GEMM, direct STG epilogue (parity-aware) ----------------
#define SM_A   0                       // 64KB
#define SM_W0  65536                   // 64KB
#define SM_W1  131072                  // 64KB
#define SM_STM 196608                  // f32[128][4]
#define SM_STS (196608 + 2048)
#define SMEM_GEMM (196608 + 4096)

__global__ void __launch_bounds__(512, 1)
gemm_mma_kernel(float* __restrict__ out, int V, int NTt, int TPC){
  extern __shared__ char smem[];
  const uint32_t sb = smem_u32(smem);
  const int tid = threadIdx.x, wid = tid >> 5, lid = tid & 31;
  const int wm = wid >> 2, wn = wid & 3;   // 4x4 warps: each m32 x n32
  const int cid = blockIdx.x, mtile = blockIdx.y;
  const int m0 = mtile * 128;
  const int nt0 = cid * TPC;
  const int nt1 = min(NTt, nt0 + TPC);
  if (nt0 >= nt1) return;

  // prologue: A fill + W(nt0) fill into local buf0
  for (int idx = tid; idx < 4096; idx += 512){
    const int r = idx >> 5, c = idx & 31;
    cp16(sb + SM_A + swoff32(r, c), &((const uint4*)g_A)[(size_t)(m0 + r)*32 + c]);
  }
  {
    const int n0 = nt0 * 128;
    for (int idx = tid; idx < 4096; idx += 512){
      const int r = idx >> 5, c = idx & 31;
      cp16(sb + SM_W0 + swoff32(r, c), &((const uint4*)g_Wt)[(size_t)(n0 + r)*32 + c]);
    }
  }
  CP_COMMIT();

  const int rA = 32*wm, rB = 32*wn;
  const int cq = (lid & 3) * 2;
  const int rq = lid >> 2;
  const int grow0 = m0 + rA + rq;            // mf=0 rows: grow0, grow0+8 (same parity)
  // V odd => row*V is 8B-aligned iff row is even. float2 STG only on even rows.
  const bool evenrow = ((grow0 & 1) == 0);
  float rm[4], rs[4];
#pragma unroll
  for (int j = 0; j < 4; j++){ rm[j] = NEG_BIG; rs[j] = 0.f; }

  for (int i = nt0; i < nt1; i++){
    const int lb = (i - nt0) & 1;            // local parity
    const uint32_t wB = sb + (lb ? SM_W1 : SM_W0);
    const int n0 = i * 128;

    CP_WAIT(0);
    __syncthreads();                         // W(i) ready; prior-iter LDSM reads done

    if (i + 1 < nt1){                        // prefetch W(i+1) into other buffer
      const uint32_t wN = sb + (lb ? SM_W0 : SM_W1);
      const int nn = (i + 1) * 128;
      for (int idx = tid; idx < 4096; idx += 512){
        const int r = idx >> 5, c = idx & 31;
        cp16(wN + swoff32(r, c), &((const uint4*)g_Wt)[(size_t)(nn + r)*32 + c]);
      }
      CP_COMMIT();
    }

    // ---- MMA: 16 k8-steps ----
    float d[2][4][4];
#pragma unroll
    for (int mf = 0; mf < 2; mf++)
#pragma unroll
      for (int nf = 0; nf < 4; nf++)
#pragma unroll
        for (int k = 0; k < 4; k++) d[mf][nf][k] = 0.f;

#pragma unroll 4
    for (int s = 0; s < 16; s++){
      const int c0 = 2*s;
      uint32_t a[2][4], b[4][2];
      ldm4(a[0], sb + SM_A, rA,      c0, lid);
      ldm4(a[1], sb + SM_A, rA + 16, c0, lid);
#pragma unroll
      for (int j = 0; j < 2; j++){
        uint32_t t[4];
        ldm4(t, wB, rB + 16*j, c0, lid);
        b[2*j][0]   = t[0]; b[2*j][1]   = t[2];
        b[2*j+1][0] = t[1]; b[2*j+1][1] = t[3];
      }
#pragma unroll
      for (int mf = 0; mf < 2; mf++)
#pragma unroll
        for (int nf = 0; nf < 4; nf++)
          mma_tf32(d[mf][nf], a[mf], b[nf]);
    }

    // ---- epilogue: direct STG (float2 on even rows, scalar on odd) + stats ----
#pragma unroll
    for (int mf = 0; mf < 2; mf++){
      const int row0 = grow0 + 16*mf;
      float* p0 = out + (size_t)row0 * V;
      float* p1 = out + (size_t)(row0 + 8) * V;
      float mx0 = NEG_BIG, mx1 = NEG_BIG;
#pragma unroll
      for (int nf = 0; nf < 4; nf++){
        const int g = n0 + rB + 8*nf + cq;
        if (g + 1 < V){
          if (evenrow){
            *(float2*)(p0 + g) = make_float2(d[mf][nf][0], d[mf][nf][1]);
            *(float2*)(p1 + g) = make_float2(d[mf][nf][2], d[mf][nf][3]);
          } else {
            p0[g]   = d[mf][nf][0];
            p0[g+1] = d[mf][nf][1];
            p1[g]   = d[mf][nf][2];
            p1[g+1] = d[mf][nf][3];
          }
        } else if (g < V){
          p0[g] = d[mf][nf][0];
          p1[g] = d[mf][nf][2];
        }
        if (g   >= V){ d[mf][nf][0] = NEG_BIG; d[mf][nf][2] = NEG_BIG; }
        if (g+1 >= V){ d[mf][nf][1] = NEG_BIG; d[mf][nf][3] = NEG_BIG; }
        mx0 = fmaxf(mx0, fmaxf(d[mf][nf][0], d[mf][nf][1]));
        mx1 = fmaxf(mx1, fmaxf(d[mf][nf][2], d[mf][nf][3]));
      }
      float s0 = 0.f, s1 = 0.f;
#pragma unroll
      for (int nf = 0; nf < 4; nf++){
        s0 += __expf(d[mf][nf][0]-mx0) + __expf(d[mf][nf][1]-mx0);
        s1 += __expf(d[mf][nf][2]-mx1) + __expf(d[mf][nf][3]-mx1);
      }
      if (mx0 == NEG_BIG) s0 = 0.f;
      if (mx1 == NEG_BIG) s1 = 0.f;
      merge(rm[2*mf],   rs[2*mf],   mx0, s0);
      merge(rm[2*mf+1], rs[2*mf+1], mx1, s1);
    }
  }

  // ---- final stats: reduce 4 lanes sharing rows, then 4 wn warps ----
  float* smM = (float*)(smem + SM_STM);
  float* smS = (float*)(smem + SM_STS);
#pragma unroll
  for (int j = 0; j < 4; j++){
#pragma unroll
    for (int o = 1; o <= 2; o <<= 1)
      merge(rm[j], rs[j], __shfl_xor_sync(0xFFFFFFFFu, rm[j], o),
                          __shfl_xor_sync(0xFFFFFFFFu, rs[j], o));
  }
  __syncthreads();
  if ((lid & 3) == 0){
#pragma unroll
    for (int j = 0; j < 4; j++){
      const int rloc = rA + 16*(j >> 1) + 8*(j & 1) + rq;
      smM[rloc*4 + wn] = rm[j];
      smS[rloc*4 + wn] = rs[j];
    }
  }
  __syncthreads();
  if (tid < 128){
    float m = NEG_BIG, s = 0.f;
#pragma unroll
    for (int k = 0; k < 4; k++) merge(m, s, smM[tid*4 + k], smS[tid*4 + k]);
    g_stats[(size_t)(m0 + tid)*NTST + cid] = make_float2(m, s);
  }
}

// ---------------- K2: combine stats -> lse ----------------
__global__ void lse_kernel(int B, int NQ){
  const int w = (blockIdx.x * blockDim.x + threadIdx.x) >> 5;
  const int lid = threadIdx.x & 31;
  if (w >= B) return;
  float m = NEG_BIG, s = 0.f;
  for (int q = lid; q < NQ; q += 32){
    const float2 t = g_stats[(size_t)w*NTST + q];
    merge(m, s, t.x, t.y);
  }
#pragma unroll
  for (int o = 16; o; o >>= 1)
    merge(m, s, __shfl_xor_sync(0xFFFFFFFFu, m, o), __shfl_xor_sync(0xFFFFFFFFu, s, o));
  if (lid == 0) g_lse[w] = m + logf(s);
}

// ---------------- K3: subtract lse in-place ----------------
__global__ void sub_kernel(float* __restrict__ out, int V){
  const int row = blockIdx.x;
  const float lse = g_lse[row];
  const int seg = (V + gridDim.y - 1) / gridDim.y;
  const int s0 = blockIdx.y * seg;
  const int s1 = min(V, s0 + seg);
  if (s0 >= s1) return;
  float* p = out + (size_t)row * V;

  int a0 = s0 + (int)(((16u - ((unsigned)(uintptr_t)(p + s0) & 15u)) & 15u) >> 2);
  if (a0 > s1) a0 = s1;
  for (int i = s0 + threadIdx.x; i < a0; i += blockDim.x) p[i] -= lse;
  const int n4 = (s1 - a0) >> 2;
  float4* p4 = (float4*)(p + a0);
  for (int j = threadIdx.x; j < n4; j += blockDim.x){
    float4 x = __ldcs(p4 + j);
    x.x -= lse; x.y -= lse; x.z -= lse; x.w -= lse;
    __stcs(p4 + j, x);
  }
  for (int i = a0 + 4*n4 + threadIdx.x; i < s1; i += blockDim.x) p[i] -= lse;
}

extern "C" void kernel_launch(void* const* d_in, const int* in_sizes, int n_in,
                              void* d_out, int out_size){
  const float* xs = (const float*)d_in[0];
  const float* EM = (const float*)d_in[2];
  const float* W  = (const float*)d_in[3];
  float* out = (float*)d_out;

  const int V   = in_sizes[3] / E_DIM;         // 50257
  const int B   = in_sizes[0] / V;             // 1024
  const int NTt = (V + 127) / 128;             // 393
  const int TPC = (NTt + NCID - 1) / NCID;     // 21
  const int NWBLK = (VPW/32) * 4;              // 6304 wsplit blocks

  cudaFuncSetAttribute(gemm_mma_kernel, cudaFuncAttributeMaxDynamicSharedMemorySize, SMEM_GEMM);

  prep_kernel<<<NWBLK + B, 256>>>(W, xs, EM, V, NWBLK);
  gemm_mma_kernel<<<dim3(NCID, B/128), 512, SMEM_GEMM>>>(out, V, NTt, TPC);
  lse_kernel<<<(B*32 + 255)/256, 256>>>(B, NCID);
  sub_kernel<<<dim3(B, 4), 256>>>(out, V);
}